// round 1
// baseline (speedup 1.0000x reference)
#include <cuda_runtime.h>
#include <cstdint>
#include <cstddef>

// CriticRNN: T=128, NE=64, NA=8, OBS=64, D=128, CH=128, VH=256, ITERS=2, B=512
// Round 1: correct fp32 pipeline.
//   emb -> gi (precomputed) -> persistent GRU scan (rows independent) ->
//   2x [a_i/a_j GEMMs, fused pairwise coupling, delta GEMMs w/ fused residual] ->
//   value head -> GEMV.

#define TBROWS 65536  // T*B

// ---------------- scratch (static device globals: no allocations) ----------------
__device__ float g_emb1[(size_t)TBROWS * 128];
__device__ float g_emb [(size_t)TBROWS * 128];
__device__ float g_gi  [(size_t)TBROWS * 384];
__device__ float g_e   [(size_t)TBROWS * 128];
__device__ float g_ai  [(size_t)TBROWS * 128];
__device__ float g_aj  [(size_t)TBROWS * 128];
__device__ float g_cat [(size_t)TBROWS * 256];
__device__ float g_d1  [(size_t)TBROWS * 128];
__device__ float g_v1  [(size_t)TBROWS * 256];
__device__ float g_v2  [(size_t)TBROWS * 256];

// ---------------- generic tiled fp32 GEMM: C = act(A[M,K] @ B[K,N] + bias) ----------------
// MODE 0: plain   MODE 1: +bias   MODE 2: relu(+bias)
// MODE 3: out = (E[m,n] + relu(x+bias)) * alive(m)   (residual + done-mask, in-place on E==C ok)
template<int MODE>
__global__ __launch_bounds__(256) void gemm_kernel(
    const float* __restrict__ A, const float* __restrict__ B, float* __restrict__ C,
    int M, int N, int K, int ldb,
    const float* __restrict__ bias, const float* __restrict__ E, const int* __restrict__ dones)
{
    __shared__ float As[16][68];
    __shared__ float Bs[16][68];
    const int tid = threadIdx.x;
    const int tx = tid & 15, ty = tid >> 4;
    const int m0 = blockIdx.y * 64, n0 = blockIdx.x * 64;
    const int arow = tid >> 2, acol = (tid & 3) << 2;   // A tile: 64x16 via float4
    const int brow = tid >> 4, bcol = (tid & 15) << 2;  // B tile: 16x64 via float4
    const float* Ap = A + (size_t)(m0 + arow) * K + acol;
    const float* Bp = B + (size_t)brow * ldb + n0 + bcol;

    float acc[4][4] = {};
    for (int k0 = 0; k0 < K; k0 += 16) {
        float4 av = *(const float4*)(Ap + k0);
        As[acol + 0][arow] = av.x; As[acol + 1][arow] = av.y;
        As[acol + 2][arow] = av.z; As[acol + 3][arow] = av.w;
        float4 bv = *(const float4*)(Bp + (size_t)k0 * ldb);
        *(float4*)&Bs[brow][bcol] = bv;
        __syncthreads();
#pragma unroll
        for (int k = 0; k < 16; k++) {
            float4 a4 = *(const float4*)&As[k][ty << 2];
            float4 b4 = *(const float4*)&Bs[k][tx << 2];
            float ar[4] = {a4.x, a4.y, a4.z, a4.w};
            float br[4] = {b4.x, b4.y, b4.z, b4.w};
#pragma unroll
            for (int i = 0; i < 4; i++)
#pragma unroll
                for (int j = 0; j < 4; j++)
                    acc[i][j] = fmaf(ar[i], br[j], acc[i][j]);
        }
        __syncthreads();
    }
#pragma unroll
    for (int i = 0; i < 4; i++) {
        const int m = m0 + (ty << 2) + i;
        float alive = 1.f;
        if (MODE == 3) alive = (dones[m] == 0) ? 1.f : 0.f;
#pragma unroll
        for (int j = 0; j < 4; j++) {
            const int n = n0 + (tx << 2) + j;
            float v = acc[i][j];
            if (MODE >= 1) v += bias[n];
            if (MODE >= 2) v = fmaxf(v, 0.f);
            if (MODE == 3) v = (E[(size_t)m * N + n] + v) * alive;
            acc[i][j] = v;
        }
        float4 o = {acc[i][0], acc[i][1], acc[i][2], acc[i][3]};
        *(float4*)(C + (size_t)m * N + n0 + (tx << 2)) = o;
    }
}

// ---------------- persistent GRU scan: 128 blocks x 4 rows, Wh in smem ----------------
// gi (with bias) precomputed. Only gh = h @ Wh is sequential, and rows are independent.
__global__ __launch_bounds__(256) void gru_kernel(
    const float* __restrict__ gi, const int* __restrict__ dones,
    const float* __restrict__ Wh, const float* __restrict__ bhn,
    const float* __restrict__ h0, float* __restrict__ e_out, float* __restrict__ h_out)
{
    extern __shared__ float sm[];
    float* whs = sm;              // 128*384 floats = 192 KB
    float* hs  = sm + 128 * 384;  // 4*128
    const int tid = threadIdx.x;
    const int col = tid & 127, rp = tid >> 7;   // rp 0 -> rows 0,1 ; rp 1 -> rows 2,3
    const int rowbase = blockIdx.x * 4;

    for (int i = tid * 4; i < 128 * 384; i += 256 * 4)
        *(float4*)(whs + i) = *(const float4*)(Wh + i);
#pragma unroll
    for (int rr = 0; rr < 2; rr++) {
        const int lr = rp * 2 + rr;
        hs[lr * 128 + col] = h0[(size_t)(rowbase + lr) * 128 + col];
    }
    const float bh = bhn[col];
    __syncthreads();

    for (int t = 0; t < 128; t++) {
        const int dbase = t * 512 + rowbase + rp * 2;
        const int d0 = dones[dbase + 0];
        const int d1 = dones[dbase + 1];
        if (d0) hs[(rp * 2 + 0) * 128 + col] = 0.f;
        if (d1) hs[(rp * 2 + 1) * 128 + col] = 0.f;
        __syncthreads();

        float a00 = 0.f, a01 = 0.f, a02 = 0.f, a10 = 0.f, a11 = 0.f, a12 = 0.f;
        const float* h0p = hs + (rp * 2 + 0) * 128;
        const float* h1p = hs + (rp * 2 + 1) * 128;
#pragma unroll 4
        for (int k = 0; k < 128; k++) {
            const float hv0 = h0p[k], hv1 = h1p[k];
            const float* w = whs + k * 384 + col;
            const float w0 = w[0], w1 = w[128], w2 = w[256];
            a00 = fmaf(hv0, w0, a00); a01 = fmaf(hv0, w1, a01); a02 = fmaf(hv0, w2, a02);
            a10 = fmaf(hv1, w0, a10); a11 = fmaf(hv1, w1, a11); a12 = fmaf(hv1, w2, a12);
        }
        __syncthreads();   // all gh reads of hs done before hs is overwritten

#pragma unroll
        for (int rr = 0; rr < 2; rr++) {
            const int lr = rp * 2 + rr;
            const int row = rowbase + lr;
            const float ar = rr ? a10 : a00;
            const float az = rr ? a11 : a01;
            const float an = rr ? a12 : a02;
            const float* gp = gi + ((size_t)t * 512 + row) * 384 + col;
            const float gr = gp[0], gz = gp[128], gn = gp[256];
            const float hold = hs[lr * 128 + col];
            const float r = 1.f / (1.f + expf(-(gr + ar)));
            const float z = 1.f / (1.f + expf(-(gz + az)));
            const float n = tanhf(gn + r * (an + bh));
            const float hnew = (1.f - z) * n + z * hold;
            const float alive = ((rr == 0 ? d0 : d1) != 0) ? 0.f : 1.f;
            e_out[((size_t)t * 512 + row) * 128 + col] = hnew * alive;
            hs[lr * 128 + col] = hnew;
        }
        __syncthreads();
    }
#pragma unroll
    for (int rr = 0; rr < 2; rr++) {
        const int lr = rp * 2 + rr;
        h_out[(size_t)(rowbase + lr) * 128 + col] = hs[lr * 128 + col];
    }
}

// ---------------- fused pairwise coupling: one block per (t, env) ----------------
// C[i][j] = sigmoid(sum_h relu(ai[i,h]+aj[j,h]+b[h]) * w[h] + b0) * alive[j] * (i != j)
// context[i] = sum_j C[i][j] * e[j];  writes cat = [e | context]  (K=256 for delta GEMM)
__global__ __launch_bounds__(128) void couple_kernel(
    const float* __restrict__ ai, const float* __restrict__ aj,
    const float* __restrict__ e, const int* __restrict__ dones,
    const float* __restrict__ chb, const float* __restrict__ cow,
    const float* __restrict__ cob, float* __restrict__ cat)
{
    __shared__ float sai[8][132], saj[8][132], se[8][132];
    __shared__ float sC[8][8], scb[128], sw[128], salive[8];
    const int tid = threadIdx.x;
    const int base = blockIdx.x * 8;  // blockIdx = t*64+env -> base = t*512 + env*8
#pragma unroll
    for (int j = 0; j < 8; j++) {
        sai[j][tid] = ai[(size_t)(base + j) * 128 + tid];
        saj[j][tid] = aj[(size_t)(base + j) * 128 + tid];
        se [j][tid] = e [(size_t)(base + j) * 128 + tid];
    }
    scb[tid] = chb[tid];
    sw[tid]  = cow[tid];
    if (tid < 8) salive[tid] = (dones[base + tid] == 0) ? 1.f : 0.f;
    __syncthreads();

    if (tid < 64) {
        const int i = tid >> 3, j = tid & 7;
        float acc = 0.f;
#pragma unroll 4
        for (int h = 0; h < 128; h++) {
            const float s = sai[i][h] + saj[j][h] + scb[h];
            acc = fmaf(fmaxf(s, 0.f), sw[h], acc);
        }
        float c = 1.f / (1.f + expf(-(acc + cob[0])));
        c *= salive[j];
        if (i == j) c = 0.f;
        sC[i][j] = c;
    }
    __syncthreads();

#pragma unroll
    for (int i = 0; i < 8; i++) {
        float acc = 0.f;
#pragma unroll
        for (int j = 0; j < 8; j++) acc = fmaf(sC[i][j], se[j][tid], acc);
        cat[(size_t)(base + i) * 256 + 128 + tid] = acc;      // context half
        cat[(size_t)(base + i) * 256 + tid]       = se[i][tid]; // e half
    }
}

// ---------------- final GEMV: values[m] = v2[m,:] . w + b ----------------
__global__ __launch_bounds__(256) void gemv_kernel(
    const float* __restrict__ v, const float* __restrict__ w,
    const float* __restrict__ b, float* __restrict__ out)
{
    const int row  = blockIdx.x * 8 + (threadIdx.x >> 5);
    const int lane = threadIdx.x & 31;
    const float* r = v + (size_t)row * 256;
    float acc = 0.f;
#pragma unroll
    for (int k = lane; k < 256; k += 32) acc = fmaf(r[k], w[k], acc);
#pragma unroll
    for (int o = 16; o; o >>= 1) acc += __shfl_xor_sync(0xffffffffu, acc, o);
    if (lane == 0) out[row] = acc + b[0];
}

// ---------------- launch ----------------
extern "C" void kernel_launch(void* const* d_in, const int* in_sizes, int n_in,
                              void* d_out, int out_size)
{
    const float* hidden = (const float*)d_in[0];   // (512,128)
    const float* obs    = (const float*)d_in[1];   // (128,512,64)
    const int*   dones  = (const int*)d_in[2];     // (128,512) — bits!=0 => done (works for i32 or f32)
    const float* e1w = (const float*)d_in[3];
    const float* e1b = (const float*)d_in[4];
    const float* e2w = (const float*)d_in[5];
    const float* e2b = (const float*)d_in[6];
    const float* Wi  = (const float*)d_in[7];
    const float* bi  = (const float*)d_in[8];
    const float* Wh  = (const float*)d_in[9];
    const float* bhn = (const float*)d_in[10];
    const float* chw = (const float*)d_in[11];   // (256,128): rows 0..127 = W1, 128..255 = W2
    const float* chb = (const float*)d_in[12];
    const float* cow = (const float*)d_in[13];   // (128,1)
    const float* cob = (const float*)d_in[14];
    const float* uhw = (const float*)d_in[15];   // (256,128)
    const float* uhb = (const float*)d_in[16];
    const float* uow = (const float*)d_in[17];   // (128,128)
    const float* uob = (const float*)d_in[18];
    const float* v1w = (const float*)d_in[19];   // (128,256)
    const float* v1b = (const float*)d_in[20];
    const float* v2w = (const float*)d_in[21];   // (256,256)
    const float* v2b = (const float*)d_in[22];
    const float* vow = (const float*)d_in[23];   // (256,1)
    const float* vob = (const float*)d_in[24];
    float* out = (float*)d_out;                  // [hidden 65536 | values 65536]

    float *emb1, *emb, *gi, *e, *ai, *aj, *cat, *d1, *v1, *v2;
    cudaGetSymbolAddress((void**)&emb1, g_emb1);
    cudaGetSymbolAddress((void**)&emb,  g_emb);
    cudaGetSymbolAddress((void**)&gi,   g_gi);
    cudaGetSymbolAddress((void**)&e,    g_e);
    cudaGetSymbolAddress((void**)&ai,   g_ai);
    cudaGetSymbolAddress((void**)&aj,   g_aj);
    cudaGetSymbolAddress((void**)&cat,  g_cat);
    cudaGetSymbolAddress((void**)&d1,   g_d1);
    cudaGetSymbolAddress((void**)&v1,   g_v1);
    cudaGetSymbolAddress((void**)&v2,   g_v2);

    const int gru_smem = 128 * 384 * 4 + 4 * 128 * 4;   // ~198.7 KB
    cudaFuncSetAttribute(gru_kernel, cudaFuncAttributeMaxDynamicSharedMemorySize, gru_smem);

    const dim3 thr(256);
    const dim3 gN128(2, 1024), gN256(4, 1024), gN384(6, 1024);

    // embed
    gemm_kernel<2><<<gN128, thr>>>(obs,  e1w, emb1, TBROWS, 128,  64, 128, e1b, nullptr, nullptr);
    gemm_kernel<2><<<gN128, thr>>>(emb1, e2w, emb,  TBROWS, 128, 128, 128, e2b, nullptr, nullptr);
    // gi for all timesteps (hoisted out of the scan)
    gemm_kernel<1><<<gN384, thr>>>(emb,  Wi,  gi,   TBROWS, 384, 128, 384, bi,  nullptr, nullptr);
    // sequential GRU (rows independent -> no grid sync)
    gru_kernel<<<128, 256, gru_smem>>>(gi, dones, Wh, bhn, hidden, e, out);

    // coupling iterations
    for (int it = 0; it < 2; it++) {
        gemm_kernel<0><<<gN128, thr>>>(e, chw,             ai, TBROWS, 128, 128, 128, nullptr, nullptr, nullptr);
        gemm_kernel<0><<<gN128, thr>>>(e, chw + 128 * 128, aj, TBROWS, 128, 128, 128, nullptr, nullptr, nullptr);
        couple_kernel<<<8192, 128>>>(ai, aj, e, dones, chb, cow, cob, cat);
        gemm_kernel<2><<<gN128, thr>>>(cat, uhw, d1, TBROWS, 128, 256, 128, uhb, nullptr, nullptr);
        gemm_kernel<3><<<gN128, thr>>>(d1,  uow, e,  TBROWS, 128, 128, 128, uob, e, dones);
    }

    // value head
    gemm_kernel<2><<<gN256, thr>>>(e,  v1w, v1, TBROWS, 256, 128, 256, v1b, nullptr, nullptr);
    gemm_kernel<2><<<gN256, thr>>>(v1, v2w, v2, TBROWS, 256, 256, 256, v2b, nullptr, nullptr);
    gemv_kernel<<<8192, 256>>>(v2, vow, vob, out + 65536);
}

// round 2
// speedup vs baseline: 1.3966x; 1.3966x over previous
#include <cuda_runtime.h>
#include <cstdint>
#include <cstddef>

// CriticRNN: T=128, NE=64, NA=8, OBS=64, D=128, CH=128, VH=256, ITERS=2, B=512
// Round 2: tf32 tensor-core GEMMs (mma.sync m16n8k8) + smem-restructured GRU.

#define TBROWS 65536  // T*B

// ---------------- scratch (static device globals) ----------------
__device__ float g_emb1[(size_t)TBROWS * 128];
__device__ float g_emb [(size_t)TBROWS * 128];
__device__ float g_gi  [(size_t)TBROWS * 384];
__device__ float g_e   [(size_t)TBROWS * 128];
__device__ float g_ai  [(size_t)TBROWS * 128];
__device__ float g_aj  [(size_t)TBROWS * 128];
__device__ float g_cat [(size_t)TBROWS * 256];
__device__ float g_d1  [(size_t)TBROWS * 128];
__device__ float g_v1  [(size_t)TBROWS * 256];
__device__ float g_v2  [(size_t)TBROWS * 256];

__device__ __forceinline__ uint32_t f2tf32(float x) {
    uint32_t u; asm("cvt.rna.tf32.f32 %0, %1;" : "=r"(u) : "f"(x)); return u;
}

__device__ __forceinline__ void mma8(float c[4],
    uint32_t a0, uint32_t a1, uint32_t a2, uint32_t a3, uint32_t b0, uint32_t b1)
{
    asm volatile(
        "mma.sync.aligned.m16n8k8.row.col.f32.tf32.tf32.f32 "
        "{%0,%1,%2,%3},{%4,%5,%6,%7},{%8,%9},{%0,%1,%2,%3};"
        : "+f"(c[0]), "+f"(c[1]), "+f"(c[2]), "+f"(c[3])
        : "r"(a0), "r"(a1), "r"(a2), "r"(a3), "r"(b0), "r"(b1));
}

// ---------------- tf32 GEMM: C = act(A[M,K] @ B[K,N] + bias) ----------------
// block tile 128x128, 8 warps (2x4), warp tile 64x32, k-chunk 32.
// MODE 0: plain  1: +bias  2: relu(+bias)  3: (E + relu(x+bias)) * alive(m)
template<int MODE>
__global__ __launch_bounds__(256) void gemm_tf32(
    const float* __restrict__ A, const float* __restrict__ B, float* __restrict__ C,
    int M, int N, int K,
    const float* __restrict__ bias, const float* __restrict__ E, const int* __restrict__ dones)
{
    __shared__ uint32_t As[128 * 36];   // rows 0..127, k-cols 0..31, stride 36 (bank-exact)
    __shared__ uint32_t Bs[32 * 136];   // k-rows 0..31, n-cols 0..127, stride 136

    const int tid = threadIdx.x;
    const int m0 = blockIdx.y * 128, n0 = blockIdx.x * 128;
    const int warp = tid >> 5, lane = tid & 31;
    const int g = lane >> 2, t4 = lane & 3;
    const int wm0 = (warp >> 2) * 64, wn0 = (warp & 3) * 32;

    float4 pa[4], pb[4];

    float acc[4][4][4];
#pragma unroll
    for (int mt = 0; mt < 4; mt++)
#pragma unroll
        for (int nt = 0; nt < 4; nt++)
#pragma unroll
            for (int q = 0; q < 4; q++) acc[mt][nt][q] = 0.f;

#define LDG_CHUNK(k0)                                                          \
    {                                                                          \
        _Pragma("unroll")                                                      \
        for (int i = 0; i < 4; i++) {                                          \
            int f = i * 256 + tid; int r = f >> 3, c = (f & 7) << 2;           \
            pa[i] = *(const float4*)(A + (size_t)(m0 + r) * K + (k0) + c);     \
        }                                                                      \
        _Pragma("unroll")                                                      \
        for (int i = 0; i < 4; i++) {                                          \
            int f = i * 256 + tid; int r = f >> 5, c = (f & 31) << 2;          \
            pb[i] = *(const float4*)(B + (size_t)((k0) + r) * N + n0 + c);     \
        }                                                                      \
    }

#define STS_CHUNK()                                                            \
    {                                                                          \
        _Pragma("unroll")                                                      \
        for (int i = 0; i < 4; i++) {                                          \
            int f = i * 256 + tid; int r = f >> 3, c = (f & 7) << 2;           \
            uint4 v; v.x = f2tf32(pa[i].x); v.y = f2tf32(pa[i].y);             \
            v.z = f2tf32(pa[i].z); v.w = f2tf32(pa[i].w);                      \
            *(uint4*)&As[r * 36 + c] = v;                                      \
        }                                                                      \
        _Pragma("unroll")                                                      \
        for (int i = 0; i < 4; i++) {                                          \
            int f = i * 256 + tid; int r = f >> 5, c = (f & 31) << 2;          \
            uint4 v; v.x = f2tf32(pb[i].x); v.y = f2tf32(pb[i].y);             \
            v.z = f2tf32(pb[i].z); v.w = f2tf32(pb[i].w);                      \
            *(uint4*)&Bs[r * 136 + c] = v;                                     \
        }                                                                      \
    }

#define COMPUTE_CHUNK()                                                        \
    {                                                                          \
        _Pragma("unroll")                                                      \
        for (int ks = 0; ks < 4; ks++) {                                       \
            uint32_t af[4][4], bf[4][2];                                       \
            const int kc = ks * 8 + t4;                                        \
            _Pragma("unroll")                                                  \
            for (int mt = 0; mt < 4; mt++) {                                   \
                int r = wm0 + mt * 16 + g;                                     \
                af[mt][0] = As[r * 36 + kc];                                   \
                af[mt][1] = As[(r + 8) * 36 + kc];                             \
                af[mt][2] = As[r * 36 + kc + 4];                               \
                af[mt][3] = As[(r + 8) * 36 + kc + 4];                         \
            }                                                                  \
            _Pragma("unroll")                                                  \
            for (int nt = 0; nt < 4; nt++) {                                   \
                int c = wn0 + nt * 8 + g;                                      \
                bf[nt][0] = Bs[kc * 136 + c];                                  \
                bf[nt][1] = Bs[(kc + 4) * 136 + c];                            \
            }                                                                  \
            _Pragma("unroll")                                                  \
            for (int mt = 0; mt < 4; mt++)                                     \
                _Pragma("unroll")                                              \
                for (int nt = 0; nt < 4; nt++)                                 \
                    mma8(acc[mt][nt], af[mt][0], af[mt][1], af[mt][2],         \
                         af[mt][3], bf[nt][0], bf[nt][1]);                     \
        }                                                                      \
    }

    LDG_CHUNK(0);
    STS_CHUNK();
    __syncthreads();
    const int nch = K >> 5;
    for (int ch = 1; ch < nch; ch++) {
        LDG_CHUNK(ch * 32);
        COMPUTE_CHUNK();
        __syncthreads();
        STS_CHUNK();
        __syncthreads();
    }
    COMPUTE_CHUNK();

    // epilogue
#pragma unroll
    for (int mt = 0; mt < 4; mt++) {
        const int r0 = m0 + wm0 + mt * 16 + g;
        float al0 = 1.f, al1 = 1.f;
        if (MODE == 3) {
            al0 = (dones[r0] == 0) ? 1.f : 0.f;
            al1 = (dones[r0 + 8] == 0) ? 1.f : 0.f;
        }
#pragma unroll
        for (int nt = 0; nt < 4; nt++) {
            const int c0 = n0 + wn0 + nt * 8 + 2 * t4;
            float b0v = 0.f, b1v = 0.f;
            if (MODE >= 1) { b0v = bias[c0]; b1v = bias[c0 + 1]; }
            float v00 = acc[mt][nt][0] + b0v, v01 = acc[mt][nt][1] + b1v;
            float v10 = acc[mt][nt][2] + b0v, v11 = acc[mt][nt][3] + b1v;
            if (MODE >= 2) {
                v00 = fmaxf(v00, 0.f); v01 = fmaxf(v01, 0.f);
                v10 = fmaxf(v10, 0.f); v11 = fmaxf(v11, 0.f);
            }
            if (MODE == 3) {
                v00 = (E[(size_t)r0 * N + c0] + v00) * al0;
                v01 = (E[(size_t)r0 * N + c0 + 1] + v01) * al0;
                v10 = (E[(size_t)(r0 + 8) * N + c0] + v10) * al1;
                v11 = (E[(size_t)(r0 + 8) * N + c0 + 1] + v11) * al1;
            }
            float2 o0; o0.x = v00; o0.y = v01;
            float2 o1; o1.x = v10; o1.y = v11;
            *(float2*)(C + (size_t)r0 * N + c0) = o0;
            *(float2*)(C + (size_t)(r0 + 8) * N + c0) = o1;
        }
    }
#undef LDG_CHUNK
#undef STS_CHUNK
#undef COMPUTE_CHUNK
}

// ---------------- GRU scan: 128 blocks x 4 rows ----------------
// whsT[g][col][k] (pad 132, k-contiguous -> conflict-free float4 LDS).
// Thread (col, rp) computes partial gh for ALL 4 rows over k-half rp;
// h loads are warp-broadcasts. Partials combined via tiny smem exchange.
__global__ __launch_bounds__(256) void gru_kernel(
    const float* __restrict__ gi, const int* __restrict__ dones,
    const float* __restrict__ Wh, const float* __restrict__ bhn,
    const float* __restrict__ h0, float* __restrict__ e_out, float* __restrict__ h_out)
{
    extern __shared__ float sm[];
    float* whsT = sm;                       // 3*128*132 = 50688 floats
    float* hs   = sm + 3 * 128 * 132;       // 4 rows * 128
    float* pex  = hs + 4 * 128;             // [row][gate][col] = 12*128
    const int tid = threadIdx.x;
    const int col = tid & 127, rp = tid >> 7;
    const int rowbase = blockIdx.x * 4;
    const int mr = rp * 2;                  // my final rows: mr, mr+1
    const int fr = (1 - rp) * 2;            // foreign rows

    // load + transpose Wh -> whsT[(g*128+cc)*132 + k]
    for (int idx = tid; idx < 128 * 384; idx += 256) {
        const int k = idx / 384, c = idx - k * 384;
        const int gg = c >> 7, cc = c & 127;
        whsT[(gg * 128 + cc) * 132 + k] = Wh[idx];
    }
    // h init, masked by done at t=0
    {
        const int d0 = dones[rowbase + mr + 0];
        const int d1 = dones[rowbase + mr + 1];
        hs[(mr + 0) * 128 + col] = d0 ? 0.f : h0[(size_t)(rowbase + mr + 0) * 128 + col];
        hs[(mr + 1) * 128 + col] = d1 ? 0.f : h0[(size_t)(rowbase + mr + 1) * 128 + col];
    }
    const float bh = bhn[col];
    __syncthreads();

    const int kbase = rp * 64;
    for (int t = 0; t < 128; t++) {
        // prefetch gi for my 2 rows + done flags (independent of hs)
        const float* gp0 = gi + ((size_t)(t * 512 + rowbase + mr) * 384) + col;
        const float* gp1 = gp0 + 384;
        const float g0r = gp0[0], g0z = gp0[128], g0n = gp0[256];
        const float g1r = gp1[0], g1z = gp1[128], g1n = gp1[256];
        const int dc0 = dones[t * 512 + rowbase + mr + 0];
        const int dc1 = dones[t * 512 + rowbase + mr + 1];
        const int dn0 = (t < 127) ? dones[(t + 1) * 512 + rowbase + mr + 0] : 0;
        const int dn1 = (t < 127) ? dones[(t + 1) * 512 + rowbase + mr + 1] : 0;

        // partial gh over my k-half for all 4 rows
        float acc[4][3];
#pragma unroll
        for (int r = 0; r < 4; r++) { acc[r][0] = 0.f; acc[r][1] = 0.f; acc[r][2] = 0.f; }
#pragma unroll
        for (int kk = 0; kk < 64; kk += 4) {
            const int k = kbase + kk;
            const float4 w0 = *(const float4*)&whsT[(0 * 128 + col) * 132 + k];
            const float4 w1 = *(const float4*)&whsT[(1 * 128 + col) * 132 + k];
            const float4 w2 = *(const float4*)&whsT[(2 * 128 + col) * 132 + k];
#pragma unroll
            for (int r = 0; r < 4; r++) {
                const float4 h = *(const float4*)&hs[r * 128 + k];
                acc[r][0] = fmaf(h.x, w0.x, fmaf(h.y, w0.y, fmaf(h.z, w0.z, fmaf(h.w, w0.w, acc[r][0]))));
                acc[r][1] = fmaf(h.x, w1.x, fmaf(h.y, w1.y, fmaf(h.z, w1.z, fmaf(h.w, w1.w, acc[r][1]))));
                acc[r][2] = fmaf(h.x, w2.x, fmaf(h.y, w2.y, fmaf(h.z, w2.z, fmaf(h.w, w2.w, acc[r][2]))));
            }
        }
        // write foreign rows' partials
#pragma unroll
        for (int rr = 0; rr < 2; rr++)
#pragma unroll
            for (int gg = 0; gg < 3; gg++)
                pex[((fr + rr) * 3 + gg) * 128 + col] = acc[fr + rr][gg];
        __syncthreads();

        // combine and do gate math for my rows
#pragma unroll
        for (int rr = 0; rr < 2; rr++) {
            const int lr = mr + rr;
            const float ar = acc[lr][0] + pex[(lr * 3 + 0) * 128 + col];
            const float az = acc[lr][1] + pex[(lr * 3 + 1) * 128 + col];
            const float an = acc[lr][2] + pex[(lr * 3 + 2) * 128 + col];
            const float gr = rr ? g1r : g0r;
            const float gz = rr ? g1z : g0z;
            const float gn = rr ? g1n : g0n;
            const float hold = hs[lr * 128 + col];
            const float r = 1.f / (1.f + expf(-(gr + ar)));
            const float z = 1.f / (1.f + expf(-(gz + az)));
            const float n = tanhf(gn + r * (an + bh));
            const float hnew = (1.f - z) * n + z * hold;
            const float alive = ((rr ? dc1 : dc0) != 0) ? 0.f : 1.f;
            e_out[((size_t)(t * 512 + rowbase + lr)) * 128 + col] = hnew * alive;
            hs[lr * 128 + col] = ((rr ? dn1 : dn0) != 0) ? 0.f : hnew;
        }
        __syncthreads();
    }
#pragma unroll
    for (int rr = 0; rr < 2; rr++)
        h_out[(size_t)(rowbase + mr + rr) * 128 + col] = hs[(mr + rr) * 128 + col];
}

// ---------------- fused pairwise coupling (unchanged) ----------------
__global__ __launch_bounds__(128) void couple_kernel(
    const float* __restrict__ ai, const float* __restrict__ aj,
    const float* __restrict__ e, const int* __restrict__ dones,
    const float* __restrict__ chb, const float* __restrict__ cow,
    const float* __restrict__ cob, float* __restrict__ cat)
{
    __shared__ float sai[8][132], saj[8][132], se[8][132];
    __shared__ float sC[8][8], scb[128], sw[128], salive[8];
    const int tid = threadIdx.x;
    const int base = blockIdx.x * 8;
#pragma unroll
    for (int j = 0; j < 8; j++) {
        sai[j][tid] = ai[(size_t)(base + j) * 128 + tid];
        saj[j][tid] = aj[(size_t)(base + j) * 128 + tid];
        se [j][tid] = e [(size_t)(base + j) * 128 + tid];
    }
    scb[tid] = chb[tid];
    sw[tid]  = cow[tid];
    if (tid < 8) salive[tid] = (dones[base + tid] == 0) ? 1.f : 0.f;
    __syncthreads();

    if (tid < 64) {
        const int i = tid >> 3, j = tid & 7;
        float acc = 0.f;
#pragma unroll 4
        for (int h = 0; h < 128; h++) {
            const float s = sai[i][h] + saj[j][h] + scb[h];
            acc = fmaf(fmaxf(s, 0.f), sw[h], acc);
        }
        float c = 1.f / (1.f + expf(-(acc + cob[0])));
        c *= salive[j];
        if (i == j) c = 0.f;
        sC[i][j] = c;
    }
    __syncthreads();

#pragma unroll
    for (int i = 0; i < 8; i++) {
        float acc = 0.f;
#pragma unroll
        for (int j = 0; j < 8; j++) acc = fmaf(sC[i][j], se[j][tid], acc);
        cat[(size_t)(base + i) * 256 + 128 + tid] = acc;
        cat[(size_t)(base + i) * 256 + tid]       = se[i][tid];
    }
}

// ---------------- final GEMV ----------------
__global__ __launch_bounds__(256) void gemv_kernel(
    const float* __restrict__ v, const float* __restrict__ w,
    const float* __restrict__ b, float* __restrict__ out)
{
    const int row  = blockIdx.x * 8 + (threadIdx.x >> 5);
    const int lane = threadIdx.x & 31;
    const float* r = v + (size_t)row * 256;
    float acc = 0.f;
#pragma unroll
    for (int k = lane; k < 256; k += 32) acc = fmaf(r[k], w[k], acc);
#pragma unroll
    for (int o = 16; o; o >>= 1) acc += __shfl_xor_sync(0xffffffffu, acc, o);
    if (lane == 0) out[row] = acc + b[0];
}

// ---------------- launch ----------------
extern "C" void kernel_launch(void* const* d_in, const int* in_sizes, int n_in,
                              void* d_out, int out_size)
{
    const float* hidden = (const float*)d_in[0];
    const float* obs    = (const float*)d_in[1];
    const int*   dones  = (const int*)d_in[2];
    const float* e1w = (const float*)d_in[3];
    const float* e1b = (const float*)d_in[4];
    const float* e2w = (const float*)d_in[5];
    const float* e2b = (const float*)d_in[6];
    const float* Wi  = (const float*)d_in[7];
    const float* bi  = (const float*)d_in[8];
    const float* Wh  = (const float*)d_in[9];
    const float* bhn = (const float*)d_in[10];
    const float* chw = (const float*)d_in[11];
    const float* chb = (const float*)d_in[12];
    const float* cow = (const float*)d_in[13];
    const float* cob = (const float*)d_in[14];
    const float* uhw = (const float*)d_in[15];
    const float* uhb = (const float*)d_in[16];
    const float* uow = (const float*)d_in[17];
    const float* uob = (const float*)d_in[18];
    const float* v1w = (const float*)d_in[19];
    const float* v1b = (const float*)d_in[20];
    const float* v2w = (const float*)d_in[21];
    const float* v2b = (const float*)d_in[22];
    const float* vow = (const float*)d_in[23];
    const float* vob = (const float*)d_in[24];
    float* out = (float*)d_out;

    float *emb1, *emb, *gi, *e, *ai, *aj, *cat, *d1, *v1, *v2;
    cudaGetSymbolAddress((void**)&emb1, g_emb1);
    cudaGetSymbolAddress((void**)&emb,  g_emb);
    cudaGetSymbolAddress((void**)&gi,   g_gi);
    cudaGetSymbolAddress((void**)&e,    g_e);
    cudaGetSymbolAddress((void**)&ai,   g_ai);
    cudaGetSymbolAddress((void**)&aj,   g_aj);
    cudaGetSymbolAddress((void**)&cat,  g_cat);
    cudaGetSymbolAddress((void**)&d1,   g_d1);
    cudaGetSymbolAddress((void**)&v1,   g_v1);
    cudaGetSymbolAddress((void**)&v2,   g_v2);

    const int gru_smem = (3 * 128 * 132 + 4 * 128 + 12 * 128) * 4;  // ~206 KB
    cudaFuncSetAttribute(gru_kernel, cudaFuncAttributeMaxDynamicSharedMemorySize, gru_smem);

    const dim3 thr(256);
    const dim3 gN128(1, 512), gN256(2, 512), gN384(3, 512);

    // embed
    gemm_tf32<2><<<gN128, thr>>>(obs,  e1w, emb1, TBROWS, 128,  64, e1b, nullptr, nullptr);
    gemm_tf32<2><<<gN128, thr>>>(emb1, e2w, emb,  TBROWS, 128, 128, e2b, nullptr, nullptr);
    // gi hoisted out of the scan
    gemm_tf32<1><<<gN384, thr>>>(emb,  Wi,  gi,   TBROWS, 384, 128, bi,  nullptr, nullptr);
    // sequential GRU
    gru_kernel<<<128, 256, gru_smem>>>(gi, dones, Wh, bhn, hidden, e, out);

    // coupling iterations
    for (int it = 0; it < 2; it++) {
        gemm_tf32<0><<<gN128, thr>>>(e, chw,             ai, TBROWS, 128, 128, nullptr, nullptr, nullptr);
        gemm_tf32<0><<<gN128, thr>>>(e, chw + 128 * 128, aj, TBROWS, 128, 128, nullptr, nullptr, nullptr);
        couple_kernel<<<8192, 128>>>(ai, aj, e, dones, chb, cow, cob, cat);
        gemm_tf32<2><<<gN128, thr>>>(cat, uhw, d1, TBROWS, 128, 256, uhb, nullptr, nullptr);
        gemm_tf32<3><<<gN128, thr>>>(d1,  uow, e,  TBROWS, 128, 128, uob, e, dones);
    }

    // value head
    gemm_tf32<2><<<gN256, thr>>>(e,  v1w, v1, TBROWS, 256, 128, v1b, nullptr, nullptr);
    gemm_tf32<2><<<gN256, thr>>>(v1, v2w, v2, TBROWS, 256, 256, v2b, nullptr, nullptr);
    gemv_kernel<<<8192, 256>>>(v2, vow, vob, out + 65536);
}

// round 4
// speedup vs baseline: 1.9979x; 1.4305x over previous
#include <cuda_runtime.h>
#include <cstdint>
#include <cstddef>

// CriticRNN: T=128, NE=64, NA=8, OBS=64, D=128, CH=128, VH=256, ITERS=2, B=512
// Round 3: GRU with register-resident Wh + packed f32x2 FMA; vectorized couple.

#define TBROWS 65536  // T*B
typedef unsigned long long ull;

// ---------------- scratch ----------------
__device__ float g_emb1[(size_t)TBROWS * 128];
__device__ float g_emb [(size_t)TBROWS * 128];
__device__ float g_gi  [(size_t)TBROWS * 384];
__device__ float g_e   [(size_t)TBROWS * 128];
__device__ float g_ai  [(size_t)TBROWS * 128];
__device__ float g_aj  [(size_t)TBROWS * 128];
__device__ float g_cat [(size_t)TBROWS * 256];
__device__ float g_d1  [(size_t)TBROWS * 128];
__device__ float g_v1  [(size_t)TBROWS * 256];
__device__ float g_v2  [(size_t)TBROWS * 256];

__device__ __forceinline__ uint32_t f2tf32(float x) {
    uint32_t u; asm("cvt.rna.tf32.f32 %0, %1;" : "=r"(u) : "f"(x)); return u;
}
__device__ __forceinline__ ull pack2(float lo, float hi) {
    ull r; asm("mov.b64 %0, {%1, %2};" : "=l"(r) : "f"(lo), "f"(hi)); return r;
}
__device__ __forceinline__ void unpack2(ull v, float& a, float& b) {
    asm("mov.b64 {%0, %1}, %2;" : "=f"(a), "=f"(b) : "l"(v));
}
__device__ __forceinline__ ull fma2(ull a, ull b, ull c) {
    ull d; asm("fma.rn.f32x2 %0, %1, %2, %3;" : "=l"(d) : "l"(a), "l"(b), "l"(c));
    return d;
}

__device__ __forceinline__ void mma8(float c[4],
    uint32_t a0, uint32_t a1, uint32_t a2, uint32_t a3, uint32_t b0, uint32_t b1)
{
    asm volatile(
        "mma.sync.aligned.m16n8k8.row.col.f32.tf32.tf32.f32 "
        "{%0,%1,%2,%3},{%4,%5,%6,%7},{%8,%9},{%0,%1,%2,%3};"
        : "+f"(c[0]), "+f"(c[1]), "+f"(c[2]), "+f"(c[3])
        : "r"(a0), "r"(a1), "r"(a2), "r"(a3), "r"(b0), "r"(b1));
}

// ---------------- tf32 GEMM (unchanged from R2) ----------------
template<int MODE>
__global__ __launch_bounds__(256) void gemm_tf32(
    const float* __restrict__ A, const float* __restrict__ B, float* __restrict__ C,
    int M, int N, int K,
    const float* __restrict__ bias, const float* __restrict__ E, const int* __restrict__ dones)
{
    __shared__ uint32_t As[128 * 36];
    __shared__ uint32_t Bs[32 * 136];

    const int tid = threadIdx.x;
    const int m0 = blockIdx.y * 128, n0 = blockIdx.x * 128;
    const int warp = tid >> 5, lane = tid & 31;
    const int g = lane >> 2, t4 = lane & 3;
    const int wm0 = (warp >> 2) * 64, wn0 = (warp & 3) * 32;

    float4 pa[4], pb[4];
    float acc[4][4][4];
#pragma unroll
    for (int mt = 0; mt < 4; mt++)
#pragma unroll
        for (int nt = 0; nt < 4; nt++)
#pragma unroll
            for (int q = 0; q < 4; q++) acc[mt][nt][q] = 0.f;

#define LDG_CHUNK(k0)                                                          \
    {                                                                          \
        _Pragma("unroll")                                                      \
        for (int i = 0; i < 4; i++) {                                          \
            int f = i * 256 + tid; int r = f >> 3, c = (f & 7) << 2;           \
            pa[i] = *(const float4*)(A + (size_t)(m0 + r) * K + (k0) + c);     \
        }                                                                      \
        _Pragma("unroll")                                                      \
        for (int i = 0; i < 4; i++) {                                          \
            int f = i * 256 + tid; int r = f >> 5, c = (f & 31) << 2;          \
            pb[i] = *(const float4*)(B + (size_t)((k0) + r) * N + n0 + c);     \
        }                                                                      \
    }

#define STS_CHUNK()                                                            \
    {                                                                          \
        _Pragma("unroll")                                                      \
        for (int i = 0; i < 4; i++) {                                          \
            int f = i * 256 + tid; int r = f >> 3, c = (f & 7) << 2;           \
            uint4 v; v.x = f2tf32(pa[i].x); v.y = f2tf32(pa[i].y);             \
            v.z = f2tf32(pa[i].z); v.w = f2tf32(pa[i].w);                      \
            *(uint4*)&As[r * 36 + c] = v;                                      \
        }                                                                      \
        _Pragma("unroll")                                                      \
        for (int i = 0; i < 4; i++) {                                          \
            int f = i * 256 + tid; int r = f >> 5, c = (f & 31) << 2;          \
            uint4 v; v.x = f2tf32(pb[i].x); v.y = f2tf32(pb[i].y);             \
            v.z = f2tf32(pb[i].z); v.w = f2tf32(pb[i].w);                      \
            *(uint4*)&Bs[r * 136 + c] = v;                                     \
        }                                                                      \
    }

#define COMPUTE_CHUNK()                                                        \
    {                                                                          \
        _Pragma("unroll")                                                      \
        for (int ks = 0; ks < 4; ks++) {                                       \
            uint32_t af[4][4], bf[4][2];                                       \
            const int kc = ks * 8 + t4;                                        \
            _Pragma("unroll")                                                  \
            for (int mt = 0; mt < 4; mt++) {                                   \
                int r = wm0 + mt * 16 + g;                                     \
                af[mt][0] = As[r * 36 + kc];                                   \
                af[mt][1] = As[(r + 8) * 36 + kc];                             \
                af[mt][2] = As[r * 36 + kc + 4];                               \
                af[mt][3] = As[(r + 8) * 36 + kc + 4];                         \
            }                                                                  \
            _Pragma("unroll")                                                  \
            for (int nt = 0; nt < 4; nt++) {                                   \
                int c = wn0 + nt * 8 + g;                                      \
                bf[nt][0] = Bs[kc * 136 + c];                                  \
                bf[nt][1] = Bs[(kc + 4) * 136 + c];                            \
            }                                                                  \
            _Pragma("unroll")                                                  \
            for (int mt = 0; mt < 4; mt++)                                     \
                _Pragma("unroll")                                              \
                for (int nt = 0; nt < 4; nt++)                                 \
                    mma8(acc[mt][nt], af[mt][0], af[mt][1], af[mt][2],         \
                         af[mt][3], bf[nt][0], bf[nt][1]);                     \
        }                                                                      \
    }

    LDG_CHUNK(0);
    STS_CHUNK();
    __syncthreads();
    const int nch = K >> 5;
    for (int ch = 1; ch < nch; ch++) {
        LDG_CHUNK(ch * 32);
        COMPUTE_CHUNK();
        __syncthreads();
        STS_CHUNK();
        __syncthreads();
    }
    COMPUTE_CHUNK();

#pragma unroll
    for (int mt = 0; mt < 4; mt++) {
        const int r0 = m0 + wm0 + mt * 16 + g;
        float al0 = 1.f, al1 = 1.f;
        if (MODE == 3) {
            al0 = (dones[r0] == 0) ? 1.f : 0.f;
            al1 = (dones[r0 + 8] == 0) ? 1.f : 0.f;
        }
#pragma unroll
        for (int nt = 0; nt < 4; nt++) {
            const int c0 = n0 + wn0 + nt * 8 + 2 * t4;
            float b0v = 0.f, b1v = 0.f;
            if (MODE >= 1) { b0v = bias[c0]; b1v = bias[c0 + 1]; }
            float v00 = acc[mt][nt][0] + b0v, v01 = acc[mt][nt][1] + b1v;
            float v10 = acc[mt][nt][2] + b0v, v11 = acc[mt][nt][3] + b1v;
            if (MODE >= 2) {
                v00 = fmaxf(v00, 0.f); v01 = fmaxf(v01, 0.f);
                v10 = fmaxf(v10, 0.f); v11 = fmaxf(v11, 0.f);
            }
            if (MODE == 3) {
                v00 = (E[(size_t)r0 * N + c0] + v00) * al0;
                v01 = (E[(size_t)r0 * N + c0 + 1] + v01) * al0;
                v10 = (E[(size_t)(r0 + 8) * N + c0] + v10) * al1;
                v11 = (E[(size_t)(r0 + 8) * N + c0 + 1] + v11) * al1;
            }
            float2 o0; o0.x = v00; o0.y = v01;
            float2 o1; o1.x = v10; o1.y = v11;
            *(float2*)(C + (size_t)r0 * N + c0) = o0;
            *(float2*)(C + (size_t)(r0 + 8) * N + c0) = o1;
        }
    }
#undef LDG_CHUNK
#undef STS_CHUNK
#undef COMPUTE_CHUNK
}

// ---------------- GRU scan: Wh in registers, packed f32x2 FMA ----------------
// 128 blocks x 4 rows. 384 threads = (col 0..127) x (gate 0..2).
// Thread holds Wh[:, gate*128+col] as 64 packed k-pairs in registers.
// h broadcast from smem as double2 (LDS.128). No cross-thread reduction needed.
__global__ __launch_bounds__(384, 1) void gru_kernel(
    const float* __restrict__ gi, const int* __restrict__ dones,
    const float* __restrict__ Wh, const float* __restrict__ bhn,
    const float* __restrict__ h0, float* __restrict__ e_out, float* __restrict__ h_out)
{
    __shared__ __align__(16) float hs[4 * 128];
    __shared__ float ghx[3 * 4 * 128];   // [gate][row][col]
    const int tid = threadIdx.x;
    const int col = tid & 127, gate = tid >> 7;   // gate 0..2
    const int rowbase = blockIdx.x * 4;

    // Wh column into registers, packed over k-pairs
    ull w2[64];
#pragma unroll
    for (int j = 0; j < 64; j++) {
        const float wa = Wh[(size_t)(2 * j) * 384 + gate * 128 + col];
        const float wb = Wh[(size_t)(2 * j + 1) * 384 + gate * 128 + col];
        w2[j] = pack2(wa, wb);
    }
    // init h (masked by done at t=0)
    for (int i = tid; i < 512; i += 384) {
        const int r = i >> 7, c = i & 127;
        const int d = dones[rowbase + r];
        hs[i] = d ? 0.f : h0[(size_t)(rowbase + r) * 128 + c];
    }
    const float bh = bhn[col];
    __syncthreads();

    const int r0 = gate;           // gate-math item 0: row = gate (0..2), col
    const bool has2 = (tid < 128); // item 1: row 3, col=tid

    for (int t = 0; t < 128; t++) {
        // prefetch gi + done flags for this thread's gate-math items
        const size_t gbase0 = ((size_t)(t * 512 + rowbase + r0)) * 384 + col;
        const float gr0 = gi[gbase0], gz0 = gi[gbase0 + 128], gn0 = gi[gbase0 + 256];
        const int dc0 = dones[t * 512 + rowbase + r0];
        const int dn0 = (t < 127) ? dones[(t + 1) * 512 + rowbase + r0] : 0;
        float gr1 = 0.f, gz1 = 0.f, gn1 = 0.f; int dc1 = 0, dn1 = 0;
        if (has2) {
            const size_t gbase1 = ((size_t)(t * 512 + rowbase + 3)) * 384 + col;
            gr1 = gi[gbase1]; gz1 = gi[gbase1 + 128]; gn1 = gi[gbase1 + 256];
            dc1 = dones[t * 512 + rowbase + 3];
            dn1 = (t < 127) ? dones[(t + 1) * 512 + rowbase + 3] : 0;
        }

        // gh partials for all 4 rows, this thread's (gate, col), full k=128
        ull acc0 = 0ull, acc1 = 0ull, acc2 = 0ull, acc3 = 0ull;
        const double2* hp = (const double2*)hs;   // row r = hp[r*32 + jj]
#pragma unroll
        for (int jj = 0; jj < 32; jj++) {
            const ull wA = w2[2 * jj], wB = w2[2 * jj + 1];
            const double2 h0v = hp[jj];
            const double2 h1v = hp[32 + jj];
            const double2 h2v = hp[64 + jj];
            const double2 h3v = hp[96 + jj];
            acc0 = fma2(wA, __double_as_longlong(h0v.x), acc0);
            acc1 = fma2(wA, __double_as_longlong(h1v.x), acc1);
            acc2 = fma2(wA, __double_as_longlong(h2v.x), acc2);
            acc3 = fma2(wA, __double_as_longlong(h3v.x), acc3);
            acc0 = fma2(wB, __double_as_longlong(h0v.y), acc0);
            acc1 = fma2(wB, __double_as_longlong(h1v.y), acc1);
            acc2 = fma2(wB, __double_as_longlong(h2v.y), acc2);
            acc3 = fma2(wB, __double_as_longlong(h3v.y), acc3);
        }
        {
            float a, b;
            unpack2(acc0, a, b); ghx[(gate * 4 + 0) * 128 + col] = a + b;
            unpack2(acc1, a, b); ghx[(gate * 4 + 1) * 128 + col] = a + b;
            unpack2(acc2, a, b); ghx[(gate * 4 + 2) * 128 + col] = a + b;
            unpack2(acc3, a, b); ghx[(gate * 4 + 3) * 128 + col] = a + b;
        }
        __syncthreads();

        // gate math: item0 = (row=gate, col); item1 = (row=3, col) for tid<128
        {
            const float ar = ghx[(0 * 4 + r0) * 128 + col];
            const float az = ghx[(1 * 4 + r0) * 128 + col];
            const float an = ghx[(2 * 4 + r0) * 128 + col];
            const float hold = hs[r0 * 128 + col];
            const float r = 1.f / (1.f + expf(-(gr0 + ar)));
            const float z = 1.f / (1.f + expf(-(gz0 + az)));
            const float n = tanhf(gn0 + r * (an + bh));
            const float hnew = (1.f - z) * n + z * hold;
            e_out[((size_t)(t * 512 + rowbase + r0)) * 128 + col] = dc0 ? 0.f : hnew;
            hs[r0 * 128 + col] = dn0 ? 0.f : hnew;
        }
        if (has2) {
            const float ar = ghx[(0 * 4 + 3) * 128 + col];
            const float az = ghx[(1 * 4 + 3) * 128 + col];
            const float an = ghx[(2 * 4 + 3) * 128 + col];
            const float hold = hs[3 * 128 + col];
            const float r = 1.f / (1.f + expf(-(gr1 + ar)));
            const float z = 1.f / (1.f + expf(-(gz1 + az)));
            const float n = tanhf(gn1 + r * (an + bh));
            const float hnew = (1.f - z) * n + z * hold;
            e_out[((size_t)(t * 512 + rowbase + 3)) * 128 + col] = dc1 ? 0.f : hnew;
            hs[3 * 128 + col] = dn1 ? 0.f : hnew;
        }
        __syncthreads();
    }
    for (int i = tid; i < 512; i += 384) {
        const int r = i >> 7, c = i & 127;
        h_out[(size_t)(rowbase + r) * 128 + c] = hs[i];
    }
}

// ---------------- fused pairwise coupling: vectorized, all threads ----------------
__global__ __launch_bounds__(128) void couple_kernel(
    const float* __restrict__ ai, const float* __restrict__ aj,
    const float* __restrict__ e, const int* __restrict__ dones,
    const float* __restrict__ chb, const float* __restrict__ cow,
    const float* __restrict__ cob, float* __restrict__ cat)
{
    __shared__ __align__(16) float sai[8 * 132];
    __shared__ __align__(16) float saj[8 * 132];
    __shared__ __align__(16) float se [8 * 132];
    __shared__ __align__(16) float scb[128];
    __shared__ __align__(16) float sw [128];
    __shared__ float sC[64], salive[8];
    const int tid = threadIdx.x;
    const int base = blockIdx.x * 8;

#pragma unroll
    for (int it = 0; it < 2; it++) {
        const int idx = it * 128 + tid;           // float4 index 0..255
        const int row = idx >> 5, c4 = (idx & 31) << 2;
        *(float4*)&sai[row * 132 + c4] = *(const float4*)(ai + (size_t)(base + row) * 128 + c4);
        *(float4*)&saj[row * 132 + c4] = *(const float4*)(aj + (size_t)(base + row) * 128 + c4);
        *(float4*)&se [row * 132 + c4] = *(const float4*)(e  + (size_t)(base + row) * 128 + c4);
    }
    scb[tid] = chb[tid];
    sw[tid]  = cow[tid];
    if (tid < 8) salive[tid] = (dones[base + tid] == 0) ? 1.f : 0.f;
    __syncthreads();

    // pair phase: 64 pairs x 2 halves (64 h-values each)
    {
        const int p = tid >> 1, half = tid & 1;
        const int i = p >> 3, j = p & 7;
        const int hb = half * 64;
        float acc = 0.f;
#pragma unroll
        for (int h4 = 0; h4 < 64; h4 += 4) {
            const float4 a = *(const float4*)&sai[i * 132 + hb + h4];
            const float4 b = *(const float4*)&saj[j * 132 + hb + h4];
            const float4 c = *(const float4*)&scb[hb + h4];
            const float4 w = *(const float4*)&sw [hb + h4];
            acc = fmaf(fmaxf(a.x + b.x + c.x, 0.f), w.x, acc);
            acc = fmaf(fmaxf(a.y + b.y + c.y, 0.f), w.y, acc);
            acc = fmaf(fmaxf(a.z + b.z + c.z, 0.f), w.z, acc);
            acc = fmaf(fmaxf(a.w + b.w + c.w, 0.f), w.w, acc);
        }
        acc += __shfl_xor_sync(0xffffffffu, acc, 1);
        if (half == 0) {
            float cc = 1.f / (1.f + expf(-(acc + cob[0])));
            cc *= salive[j];
            if (i == j) cc = 0.f;
            sC[i * 8 + j] = cc;
        }
    }
    __syncthreads();

    // context + concat
#pragma unroll
    for (int i = 0; i < 8; i++) {
        float acc = 0.f;
#pragma unroll
        for (int j = 0; j < 8; j++) acc = fmaf(sC[i * 8 + j], se[j * 132 + tid], acc);
        cat[(size_t)(base + i) * 256 + 128 + tid] = acc;
        cat[(size_t)(base + i) * 256 + tid]       = se[i * 132 + tid];
    }
}

// ---------------- final GEMV (float4) ----------------
__global__ __launch_bounds__(256) void gemv_kernel(
    const float* __restrict__ v, const float* __restrict__ w,
    const float* __restrict__ b, float* __restrict__ out)
{
    const int row  = blockIdx.x * 8 + (threadIdx.x >> 5);
    const int lane = threadIdx.x & 31;
    const float4* r4 = (const float4*)(v + (size_t)row * 256);
    const float4* w4 = (const float4*)w;
    float acc = 0.f;
#pragma unroll
    for (int kk = lane; kk < 64; kk += 32) {
        const float4 a = r4[kk], bb = w4[kk];
        acc = fmaf(a.x, bb.x, acc); acc = fmaf(a.y, bb.y, acc);
        acc = fmaf(a.z, bb.z, acc); acc = fmaf(a.w, bb.w, acc);
    }
#pragma unroll
    for (int o = 16; o; o >>= 1) acc += __shfl_xor_sync(0xffffffffu, acc, o);
    if (lane == 0) out[row] = acc + b[0];
}

// ---------------- launch ----------------
extern "C" void kernel_launch(void* const* d_in, const int* in_sizes, int n_in,
                              void* d_out, int out_size)
{
    const float* hidden = (const float*)d_in[0];
    const float* obs    = (const float*)d_in[1];
    const int*   dones  = (const int*)d_in[2];
    const float* e1w = (const float*)d_in[3];
    const float* e1b = (const float*)d_in[4];
    const float* e2w = (const float*)d_in[5];
    const float* e2b = (const float*)d_in[6];
    const float* Wi  = (const float*)d_in[7];
    const float* bi  = (const float*)d_in[8];
    const float* Wh  = (const float*)d_in[9];
    const float* bhn = (const float*)d_in[10];
    const float* chw = (const float*)d_in[11];
    const float* chb = (const float*)d_in[12];
    const float* cow = (const float*)d_in[13];
    const float* cob = (const float*)d_in[14];
    const float* uhw = (const float*)d_in[15];
    const float* uhb = (const float*)d_in[16];
    const float* uow = (const float*)d_in[17];
    const float* uob = (const float*)d_in[18];
    const float* v1w = (const float*)d_in[19];
    const float* v1b = (const float*)d_in[20];
    const float* v2w = (const float*)d_in[21];
    const float* v2b = (const float*)d_in[22];
    const float* vow = (const float*)d_in[23];
    const float* vob = (const float*)d_in[24];
    float* out = (float*)d_out;

    float *emb1, *emb, *gi, *e, *ai, *aj, *cat, *d1, *v1, *v2;
    cudaGetSymbolAddress((void**)&emb1, g_emb1);
    cudaGetSymbolAddress((void**)&emb,  g_emb);
    cudaGetSymbolAddress((void**)&gi,   g_gi);
    cudaGetSymbolAddress((void**)&e,    g_e);
    cudaGetSymbolAddress((void**)&ai,   g_ai);
    cudaGetSymbolAddress((void**)&aj,   g_aj);
    cudaGetSymbolAddress((void**)&cat,  g_cat);
    cudaGetSymbolAddress((void**)&d1,   g_d1);
    cudaGetSymbolAddress((void**)&v1,   g_v1);
    cudaGetSymbolAddress((void**)&v2,   g_v2);

    const dim3 thr(256);
    const dim3 gN128(1, 512), gN256(2, 512), gN384(3, 512);

    // embed
    gemm_tf32<2><<<gN128, thr>>>(obs,  e1w, emb1, TBROWS, 128,  64, e1b, nullptr, nullptr);
    gemm_tf32<2><<<gN128, thr>>>(emb1, e2w, emb,  TBROWS, 128, 128, e2b, nullptr, nullptr);
    // gi hoisted out of the scan
    gemm_tf32<1><<<gN384, thr>>>(emb,  Wi,  gi,   TBROWS, 384, 128, bi,  nullptr, nullptr);
    // sequential GRU
    gru_kernel<<<128, 384>>>(gi, dones, Wh, bhn, hidden, e, out);

    // coupling iterations
    for (int it = 0; it < 2; it++) {
        gemm_tf32<0><<<gN128, thr>>>(e, chw,             ai, TBROWS, 128, 128, nullptr, nullptr, nullptr);
        gemm_tf32<0><<<gN128, thr>>>(e, chw + 128 * 128, aj, TBROWS, 128, 128, nullptr, nullptr, nullptr);
        couple_kernel<<<8192, 128>>>(ai, aj, e, dones, chb, cow, cob, cat);
        gemm_tf32<2><<<gN128, thr>>>(cat, uhw, d1, TBROWS, 128, 256, uhb, nullptr, nullptr);
        gemm_tf32<3><<<gN128, thr>>>(d1,  uow, e,  TBROWS, 128, 128, uob, e, dones);
    }

    // value head
    gemm_tf32<2><<<gN256, thr>>>(e,  v1w, v1, TBROWS, 256, 128, v1b, nullptr, nullptr);
    gemm_tf32<2><<<gN256, thr>>>(v1, v2w, v2, TBROWS, 256, 256, v2b, nullptr, nullptr);
    gemv_kernel<<<8192, 256>>>(v2, vow, vob, out + 65536);
}

// round 5
// speedup vs baseline: 2.0425x; 1.0223x over previous
#include <cuda_runtime.h>
#include <cstdint>
#include <cstddef>

// CriticRNN: T=128, NE=64, NA=8, OBS=64, D=128, CH=128, VH=256, ITERS=2, B=512
// Round 5: mega-fusion. 6 launches total:
//   embed_gi_fused -> gru -> 2x(couple_fused, delta_fused) -> value_fused

#define TBROWS 65536
typedef unsigned long long ull;

// ---------------- scratch ----------------
__device__ float g_gi [(size_t)TBROWS * 384];
__device__ float g_e  [(size_t)TBROWS * 128];
__device__ float g_cat[(size_t)TBROWS * 256];

__device__ __forceinline__ uint32_t f2tf32(float x) {
    uint32_t u; asm("cvt.rna.tf32.f32 %0, %1;" : "=r"(u) : "f"(x)); return u;
}
__device__ __forceinline__ ull pack2(float lo, float hi) {
    ull r; asm("mov.b64 %0, {%1, %2};" : "=l"(r) : "f"(lo), "f"(hi)); return r;
}
__device__ __forceinline__ void unpack2(ull v, float& a, float& b) {
    asm("mov.b64 {%0, %1}, %2;" : "=f"(a), "=f"(b) : "l"(v));
}
__device__ __forceinline__ ull fma2(ull a, ull b, ull c) {
    ull d; asm("fma.rn.f32x2 %0, %1, %2, %3;" : "=l"(d) : "l"(a), "l"(b), "l"(c));
    return d;
}
__device__ __forceinline__ void mma8(float c[4],
    uint32_t a0, uint32_t a1, uint32_t a2, uint32_t a3, uint32_t b0, uint32_t b1)
{
    asm volatile(
        "mma.sync.aligned.m16n8k8.row.col.f32.tf32.tf32.f32 "
        "{%0,%1,%2,%3},{%4,%5,%6,%7},{%8,%9},{%0,%1,%2,%3};"
        : "+f"(c[0]), "+f"(c[1]), "+f"(c[2]), "+f"(c[3])
        : "r"(a0), "r"(a1), "r"(a2), "r"(a3), "r"(b0), "r"(b1));
}

// ======== shared GEMM building blocks: block tile 128x128, 8 warps (2m x 4n),
// ======== warp tile 64x32, k-chunk 32. As staging stride 36, Bs stride 136.

__device__ __forceinline__ void acc_zero(float (&acc)[4][4][4]) {
#pragma unroll
    for (int mt = 0; mt < 4; mt++)
#pragma unroll
        for (int nt = 0; nt < 4; nt++)
#pragma unroll
            for (int q = 0; q < 4; q++) acc[mt][nt][q] = 0.f;
}

// one 32-k chunk of mma work; A read from asrc (tf32, stride astr), B from Bs(136)
__device__ __forceinline__ void compute_chunk(
    const uint32_t* __restrict__ asrc, int astr, const uint32_t* __restrict__ Bs,
    float (&acc)[4][4][4], int wm0, int wn0, int g, int t4)
{
#pragma unroll
    for (int ks = 0; ks < 4; ks++) {
        const int kc = ks * 8 + t4;
        uint32_t af[4][4], bf[4][2];
#pragma unroll
        for (int mt = 0; mt < 4; mt++) {
            const int r = wm0 + mt * 16 + g;
            af[mt][0] = asrc[r * astr + kc];
            af[mt][1] = asrc[(r + 8) * astr + kc];
            af[mt][2] = asrc[r * astr + kc + 4];
            af[mt][3] = asrc[(r + 8) * astr + kc + 4];
        }
#pragma unroll
        for (int nt = 0; nt < 4; nt++) {
            const int c = wn0 + nt * 8 + g;
            bf[nt][0] = Bs[kc * 136 + c];
            bf[nt][1] = Bs[(kc + 4) * 136 + c];
        }
#pragma unroll
        for (int mt = 0; mt < 4; mt++)
#pragma unroll
            for (int nt = 0; nt < 4; nt++)
                mma8(acc[mt][nt], af[mt][0], af[mt][1], af[mt][2], af[mt][3],
                     bf[nt][0], bf[nt][1]);
    }
}

// GEMM pass, A from gmem (fp32, row-major, lda), B from gmem (fp32 weights, ldb).
// A is the block-row base pointer (row 0 of this block). K multiple of 32.
__device__ __forceinline__ void gemm_gmemA(
    const float* __restrict__ A, int lda, int K,
    const float* __restrict__ B, int ldb,
    uint32_t* As, uint32_t* Bs, float (&acc)[4][4][4],
    int tid, int wm0, int wn0, int g, int t4)
{
    acc_zero(acc);
    float4 pa[4], pb[4];
    const int nch = K >> 5;
    __syncthreads();   // protect staging buffers from previous pass readers
#pragma unroll
    for (int i = 0; i < 4; i++) {
        const int f = i * 256 + tid; const int r = f >> 3, c = (f & 7) << 2;
        pa[i] = *(const float4*)(A + (size_t)r * lda + c);
    }
#pragma unroll
    for (int i = 0; i < 4; i++) {
        const int f = i * 256 + tid; const int r = f >> 5, c = (f & 31) << 2;
        pb[i] = *(const float4*)(B + (size_t)r * ldb + c);
    }
#pragma unroll
    for (int i = 0; i < 4; i++) {
        const int f = i * 256 + tid; const int r = f >> 3, c = (f & 7) << 2;
        uint4 v; v.x = f2tf32(pa[i].x); v.y = f2tf32(pa[i].y);
        v.z = f2tf32(pa[i].z); v.w = f2tf32(pa[i].w);
        *(uint4*)&As[r * 36 + c] = v;
    }
#pragma unroll
    for (int i = 0; i < 4; i++) {
        const int f = i * 256 + tid; const int r = f >> 5, c = (f & 31) << 2;
        uint4 v; v.x = f2tf32(pb[i].x); v.y = f2tf32(pb[i].y);
        v.z = f2tf32(pb[i].z); v.w = f2tf32(pb[i].w);
        *(uint4*)&Bs[r * 136 + c] = v;
    }
    __syncthreads();
    for (int ch = 1; ch < nch; ch++) {
        const int k0 = ch * 32;
#pragma unroll
        for (int i = 0; i < 4; i++) {
            const int f = i * 256 + tid; const int r = f >> 3, c = (f & 7) << 2;
            pa[i] = *(const float4*)(A + (size_t)r * lda + k0 + c);
        }
#pragma unroll
        for (int i = 0; i < 4; i++) {
            const int f = i * 256 + tid; const int r = f >> 5, c = (f & 31) << 2;
            pb[i] = *(const float4*)(B + (size_t)(k0 + r) * ldb + c);
        }
        compute_chunk(As, 36, Bs, acc, wm0, wn0, g, t4);
        __syncthreads();
#pragma unroll
        for (int i = 0; i < 4; i++) {
            const int f = i * 256 + tid; const int r = f >> 3, c = (f & 7) << 2;
            uint4 v; v.x = f2tf32(pa[i].x); v.y = f2tf32(pa[i].y);
            v.z = f2tf32(pa[i].z); v.w = f2tf32(pa[i].w);
            *(uint4*)&As[r * 36 + c] = v;
        }
#pragma unroll
        for (int i = 0; i < 4; i++) {
            const int f = i * 256 + tid; const int r = f >> 5, c = (f & 31) << 2;
            uint4 v; v.x = f2tf32(pb[i].x); v.y = f2tf32(pb[i].y);
            v.z = f2tf32(pb[i].z); v.w = f2tf32(pb[i].w);
            *(uint4*)&Bs[r * 136 + c] = v;
        }
        __syncthreads();
    }
    compute_chunk(As, 36, Bs, acc, wm0, wn0, g, t4);
}

// GEMM pass, A resident in smem as tf32 (stride astr), B streamed from gmem.
__device__ __forceinline__ void gemm_smemA(
    const uint32_t* __restrict__ Asrc, int astr, int K,
    const float* __restrict__ B, int ldb,
    uint32_t* Bs, float (&acc)[4][4][4],
    int tid, int wm0, int wn0, int g, int t4)
{
    acc_zero(acc);
    float4 pb[4];
    const int nch = K >> 5;
    __syncthreads();
#pragma unroll
    for (int i = 0; i < 4; i++) {
        const int f = i * 256 + tid; const int r = f >> 5, c = (f & 31) << 2;
        pb[i] = *(const float4*)(B + (size_t)r * ldb + c);
    }
#pragma unroll
    for (int i = 0; i < 4; i++) {
        const int f = i * 256 + tid; const int r = f >> 5, c = (f & 31) << 2;
        uint4 v; v.x = f2tf32(pb[i].x); v.y = f2tf32(pb[i].y);
        v.z = f2tf32(pb[i].z); v.w = f2tf32(pb[i].w);
        *(uint4*)&Bs[r * 136 + c] = v;
    }
    __syncthreads();
    for (int ch = 1; ch < nch; ch++) {
        const int k0 = ch * 32;
#pragma unroll
        for (int i = 0; i < 4; i++) {
            const int f = i * 256 + tid; const int r = f >> 5, c = (f & 31) << 2;
            pb[i] = *(const float4*)(B + (size_t)(k0 + r) * ldb + c);
        }
        compute_chunk(Asrc + (ch - 1) * 32, astr, Bs, acc, wm0, wn0, g, t4);
        __syncthreads();
#pragma unroll
        for (int i = 0; i < 4; i++) {
            const int f = i * 256 + tid; const int r = f >> 5, c = (f & 31) << 2;
            uint4 v; v.x = f2tf32(pb[i].x); v.y = f2tf32(pb[i].y);
            v.z = f2tf32(pb[i].z); v.w = f2tf32(pb[i].w);
            *(uint4*)&Bs[r * 136 + c] = v;
        }
        __syncthreads();
    }
    compute_chunk(Asrc + (nch - 1) * 32, astr, Bs, acc, wm0, wn0, g, t4);
}

// ================= kernel D: obs -> emb1 -> emb -> gi =================
__global__ __launch_bounds__(256) void embed_gi_fused(
    const float* __restrict__ obs,
    const float* __restrict__ e1w, const float* __restrict__ e1b,
    const float* __restrict__ e2w, const float* __restrict__ e2b,
    const float* __restrict__ Wi,  const float* __restrict__ bi,
    float* __restrict__ gi)
{
    extern __shared__ unsigned char smraw[];
    uint32_t* As = (uint32_t*)smraw;                       // 128*36
    uint32_t* Bs = As + 128 * 36;                          // 32*136
    uint32_t* s1 = Bs + 32 * 136;                          // 128*132
    uint32_t* s2 = s1 + 128 * 132;                         // 128*132

    const int tid = threadIdx.x;
    const int warp = tid >> 5, lane = tid & 31;
    const int g = lane >> 2, t4 = lane & 3;
    const int wm0 = (warp >> 2) * 64, wn0 = (warp & 3) * 32;
    const int br0 = blockIdx.x * 128;
    float acc[4][4][4];

    // pass 1: emb1 = relu(obs @ e1w + b)
    gemm_gmemA(obs + (size_t)br0 * 64, 64, 64, e1w, 128, As, Bs, acc, tid, wm0, wn0, g, t4);
#pragma unroll
    for (int mt = 0; mt < 4; mt++)
#pragma unroll
        for (int nt = 0; nt < 4; nt++) {
            const int r0 = wm0 + mt * 16 + g, c0 = wn0 + nt * 8 + 2 * t4;
            const float b0 = e1b[c0], b1 = e1b[c0 + 1];
            s1[r0 * 132 + c0]           = f2tf32(fmaxf(acc[mt][nt][0] + b0, 0.f));
            s1[r0 * 132 + c0 + 1]       = f2tf32(fmaxf(acc[mt][nt][1] + b1, 0.f));
            s1[(r0 + 8) * 132 + c0]     = f2tf32(fmaxf(acc[mt][nt][2] + b0, 0.f));
            s1[(r0 + 8) * 132 + c0 + 1] = f2tf32(fmaxf(acc[mt][nt][3] + b1, 0.f));
        }

    // pass 2: emb = relu(emb1 @ e2w + b)
    gemm_smemA(s1, 132, 128, e2w, 128, Bs, acc, tid, wm0, wn0, g, t4);
    __syncthreads();   // all reads of s1 complete; now write s2 (and next pass reuses Bs)
#pragma unroll
    for (int mt = 0; mt < 4; mt++)
#pragma unroll
        for (int nt = 0; nt < 4; nt++) {
            const int r0 = wm0 + mt * 16 + g, c0 = wn0 + nt * 8 + 2 * t4;
            const float b0 = e2b[c0], b1 = e2b[c0 + 1];
            s2[r0 * 132 + c0]           = f2tf32(fmaxf(acc[mt][nt][0] + b0, 0.f));
            s2[r0 * 132 + c0 + 1]       = f2tf32(fmaxf(acc[mt][nt][1] + b1, 0.f));
            s2[(r0 + 8) * 132 + c0]     = f2tf32(fmaxf(acc[mt][nt][2] + b0, 0.f));
            s2[(r0 + 8) * 132 + c0 + 1] = f2tf32(fmaxf(acc[mt][nt][3] + b1, 0.f));
        }

    // pass 3: gi = emb @ Wi + bi  (N=384 in 3 sub-passes)
    for (int p = 0; p < 3; p++) {
        gemm_smemA(s2, 132, 128, Wi + p * 128, 384, Bs, acc, tid, wm0, wn0, g, t4);
#pragma unroll
        for (int mt = 0; mt < 4; mt++)
#pragma unroll
            for (int nt = 0; nt < 4; nt++) {
                const int r0 = wm0 + mt * 16 + g, c0 = wn0 + nt * 8 + 2 * t4;
                const int cg = p * 128 + c0;
                const float b0 = bi[cg], b1 = bi[cg + 1];
                float2 o0 = {acc[mt][nt][0] + b0, acc[mt][nt][1] + b1};
                float2 o1 = {acc[mt][nt][2] + b0, acc[mt][nt][3] + b1};
                *(float2*)(gi + (size_t)(br0 + r0) * 384 + cg) = o0;
                *(float2*)(gi + (size_t)(br0 + r0 + 8) * 384 + cg) = o1;
            }
    }
}

// ================= GRU (unchanged from R4) =================
__global__ __launch_bounds__(384, 1) void gru_kernel(
    const float* __restrict__ gi, const int* __restrict__ dones,
    const float* __restrict__ Wh, const float* __restrict__ bhn,
    const float* __restrict__ h0, float* __restrict__ e_out, float* __restrict__ h_out)
{
    __shared__ __align__(16) float hs[4 * 128];
    __shared__ float ghx[3 * 4 * 128];
    const int tid = threadIdx.x;
    const int col = tid & 127, gate = tid >> 7;
    const int rowbase = blockIdx.x * 4;

    ull w2[64];
#pragma unroll
    for (int j = 0; j < 64; j++) {
        const float wa = Wh[(size_t)(2 * j) * 384 + gate * 128 + col];
        const float wb = Wh[(size_t)(2 * j + 1) * 384 + gate * 128 + col];
        w2[j] = pack2(wa, wb);
    }
    for (int i = tid; i < 512; i += 384) {
        const int r = i >> 7, c = i & 127;
        const int d = dones[rowbase + r];
        hs[i] = d ? 0.f : h0[(size_t)(rowbase + r) * 128 + c];
    }
    const float bh = bhn[col];
    __syncthreads();

    const int r0 = gate;
    const bool has2 = (tid < 128);

    for (int t = 0; t < 128; t++) {
        const size_t gbase0 = ((size_t)(t * 512 + rowbase + r0)) * 384 + col;
        const float gr0 = gi[gbase0], gz0 = gi[gbase0 + 128], gn0 = gi[gbase0 + 256];
        const int dc0 = dones[t * 512 + rowbase + r0];
        const int dn0 = (t < 127) ? dones[(t + 1) * 512 + rowbase + r0] : 0;
        float gr1 = 0.f, gz1 = 0.f, gn1 = 0.f; int dc1 = 0, dn1 = 0;
        if (has2) {
            const size_t gbase1 = ((size_t)(t * 512 + rowbase + 3)) * 384 + col;
            gr1 = gi[gbase1]; gz1 = gi[gbase1 + 128]; gn1 = gi[gbase1 + 256];
            dc1 = dones[t * 512 + rowbase + 3];
            dn1 = (t < 127) ? dones[(t + 1) * 512 + rowbase + 3] : 0;
        }

        ull acc0 = 0ull, acc1 = 0ull, acc2 = 0ull, acc3 = 0ull;
        const double2* hp = (const double2*)hs;
#pragma unroll
        for (int jj = 0; jj < 32; jj++) {
            const ull wA = w2[2 * jj], wB = w2[2 * jj + 1];
            const double2 h0v = hp[jj];
            const double2 h1v = hp[32 + jj];
            const double2 h2v = hp[64 + jj];
            const double2 h3v = hp[96 + jj];
            acc0 = fma2(wA, __double_as_longlong(h0v.x), acc0);
            acc1 = fma2(wA, __double_as_longlong(h1v.x), acc1);
            acc2 = fma2(wA, __double_as_longlong(h2v.x), acc2);
            acc3 = fma2(wA, __double_as_longlong(h3v.x), acc3);
            acc0 = fma2(wB, __double_as_longlong(h0v.y), acc0);
            acc1 = fma2(wB, __double_as_longlong(h1v.y), acc1);
            acc2 = fma2(wB, __double_as_longlong(h2v.y), acc2);
            acc3 = fma2(wB, __double_as_longlong(h3v.y), acc3);
        }
        {
            float a, b;
            unpack2(acc0, a, b); ghx[(gate * 4 + 0) * 128 + col] = a + b;
            unpack2(acc1, a, b); ghx[(gate * 4 + 1) * 128 + col] = a + b;
            unpack2(acc2, a, b); ghx[(gate * 4 + 2) * 128 + col] = a + b;
            unpack2(acc3, a, b); ghx[(gate * 4 + 3) * 128 + col] = a + b;
        }
        __syncthreads();

        {
            const float ar = ghx[(0 * 4 + r0) * 128 + col];
            const float az = ghx[(1 * 4 + r0) * 128 + col];
            const float an = ghx[(2 * 4 + r0) * 128 + col];
            const float hold = hs[r0 * 128 + col];
            const float r = 1.f / (1.f + expf(-(gr0 + ar)));
            const float z = 1.f / (1.f + expf(-(gz0 + az)));
            const float n = tanhf(gn0 + r * (an + bh));
            const float hnew = (1.f - z) * n + z * hold;
            e_out[((size_t)(t * 512 + rowbase + r0)) * 128 + col] = dc0 ? 0.f : hnew;
            hs[r0 * 128 + col] = dn0 ? 0.f : hnew;
        }
        if (has2) {
            const float ar = ghx[(0 * 4 + 3) * 128 + col];
            const float az = ghx[(1 * 4 + 3) * 128 + col];
            const float an = ghx[(2 * 4 + 3) * 128 + col];
            const float hold = hs[3 * 128 + col];
            const float r = 1.f / (1.f + expf(-(gr1 + ar)));
            const float z = 1.f / (1.f + expf(-(gz1 + az)));
            const float n = tanhf(gn1 + r * (an + bh));
            const float hnew = (1.f - z) * n + z * hold;
            e_out[((size_t)(t * 512 + rowbase + 3)) * 128 + col] = dc1 ? 0.f : hnew;
            hs[3 * 128 + col] = dn1 ? 0.f : hnew;
        }
        __syncthreads();
    }
    for (int i = tid; i < 512; i += 384) {
        const int r = i >> 7, c = i & 127;
        h_out[(size_t)(rowbase + r) * 128 + c] = hs[i];
    }
}

// ================= kernel A: e -> ai,aj -> pairwise -> cat =================
__global__ __launch_bounds__(256) void couple_fused(
    const float* __restrict__ e, const float* __restrict__ chw,
    const float* __restrict__ chb, const float* __restrict__ cow,
    const float* __restrict__ cob, const int* __restrict__ dones,
    float* __restrict__ cat)
{
    extern __shared__ unsigned char smraw[];
    uint32_t* As = (uint32_t*)smraw;                 // 128*36
    uint32_t* Bs = As + 128 * 36;                    // 32*136
    float* sai = (float*)(Bs + 32 * 136);            // 128*132
    float* saj = sai + 128 * 132;                    // 128*132
    float* scb = saj + 128 * 132;                    // 128
    float* sw  = scb + 128;                          // 128
    float* salive = sw + 128;                        // 128
    float* sC  = salive + 128;                       // 16*64

    const int tid = threadIdx.x;
    const int warp = tid >> 5, lane = tid & 31;
    const int g = lane >> 2, t4 = lane & 3;
    const int wm0 = (warp >> 2) * 64, wn0 = (warp & 3) * 32;
    const int br0 = blockIdx.x * 128;
    float acc[4][4][4];

    if (tid < 128) {
        scb[tid] = chb[tid];
        sw[tid]  = cow[tid];
        salive[tid] = (dones[br0 + tid] == 0) ? 1.f : 0.f;
    }

    // pass 0: ai = e @ W1 ; pass 1: aj = e @ W2
    for (int p = 0; p < 2; p++) {
        gemm_gmemA(e + (size_t)br0 * 128, 128, 128, chw + p * 128 * 128, 128,
                   As, Bs, acc, tid, wm0, wn0, g, t4);
        float* dst = p ? saj : sai;
#pragma unroll
        for (int mt = 0; mt < 4; mt++)
#pragma unroll
            for (int nt = 0; nt < 4; nt++) {
                const int r0 = wm0 + mt * 16 + g, c0 = wn0 + nt * 8 + 2 * t4;
                dst[r0 * 132 + c0]           = acc[mt][nt][0];
                dst[r0 * 132 + c0 + 1]       = acc[mt][nt][1];
                dst[(r0 + 8) * 132 + c0]     = acc[mt][nt][2];
                dst[(r0 + 8) * 132 + c0 + 1] = acc[mt][nt][3];
            }
    }
    __syncthreads();

    // pairwise: 16 groups x 64 pairs; thread -> (group, i, j-quad)
    {
        const int grp = tid >> 4, s = tid & 15;
        const int i = s >> 1, jh = s & 1;
        const float cob0 = __ldg(cob);
        float a4[4] = {0.f, 0.f, 0.f, 0.f};
#pragma unroll 8
        for (int h = 0; h < 128; h += 4) {
            const float4 av = *(const float4*)&sai[(grp * 8 + i) * 132 + h];
            const float4 cb = *(const float4*)&scb[h];
            const float4 wv = *(const float4*)&sw[h];
#pragma unroll
            for (int jj = 0; jj < 4; jj++) {
                const int j = jh * 4 + jj;
                const float4 bv = *(const float4*)&saj[(grp * 8 + j) * 132 + h];
                a4[jj] = fmaf(fmaxf(av.x + bv.x + cb.x, 0.f), wv.x, a4[jj]);
                a4[jj] = fmaf(fmaxf(av.y + bv.y + cb.y, 0.f), wv.y, a4[jj]);
                a4[jj] = fmaf(fmaxf(av.z + bv.z + cb.z, 0.f), wv.z, a4[jj]);
                a4[jj] = fmaf(fmaxf(av.w + bv.w + cb.w, 0.f), wv.w, a4[jj]);
            }
        }
#pragma unroll
        for (int jj = 0; jj < 4; jj++) {
            const int j = jh * 4 + jj;
            float c = 1.f / (1.f + expf(-(a4[jj] + cob0)));
            c *= salive[grp * 8 + j];
            if (i == j) c = 0.f;
            sC[grp * 64 + i * 8 + j] = c;
        }
    }
    __syncthreads();

    // context + cat: thread = (gh, col); 8 groups each
    {
        const int colt = tid & 127, gh = tid >> 7;
#pragma unroll
        for (int gg = 0; gg < 8; gg++) {
            const int grp = gh * 8 + gg;
            const int rbase = br0 + grp * 8;
            float ev[8];
#pragma unroll
            for (int j = 0; j < 8; j++) ev[j] = e[(size_t)(rbase + j) * 128 + colt];
#pragma unroll
            for (int i = 0; i < 8; i++) {
                float ctx = 0.f;
#pragma unroll
                for (int j = 0; j < 8; j++)
                    ctx = fmaf(sC[grp * 64 + i * 8 + j], ev[j], ctx);
                cat[(size_t)(rbase + i) * 256 + colt]       = ev[i];
                cat[(size_t)(rbase + i) * 256 + 128 + colt] = ctx;
            }
        }
    }
}

// ================= kernel B: cat -> d1 -> e update =================
__global__ __launch_bounds__(256) void delta_fused(
    const float* __restrict__ cat,
    const float* __restrict__ uhw, const float* __restrict__ uhb,
    const float* __restrict__ uow, const float* __restrict__ uob,
    const int* __restrict__ dones, float* __restrict__ e)
{
    extern __shared__ unsigned char smraw[];
    uint32_t* As  = (uint32_t*)smraw;      // 128*36
    uint32_t* Bs  = As + 128 * 36;         // 32*136
    uint32_t* d1s = Bs + 32 * 136;         // 128*132

    const int tid = threadIdx.x;
    const int warp = tid >> 5, lane = tid & 31;
    const int g = lane >> 2, t4 = lane & 3;
    const int wm0 = (warp >> 2) * 64, wn0 = (warp & 3) * 32;
    const int br0 = blockIdx.x * 128;
    float acc[4][4][4];

    // d1 = relu(cat @ Uh + b)
    gemm_gmemA(cat + (size_t)br0 * 256, 256, 256, uhw, 128, As, Bs, acc, tid, wm0, wn0, g, t4);
#pragma unroll
    for (int mt = 0; mt < 4; mt++)
#pragma unroll
        for (int nt = 0; nt < 4; nt++) {
            const int r0 = wm0 + mt * 16 + g, c0 = wn0 + nt * 8 + 2 * t4;
            const float b0 = uhb[c0], b1 = uhb[c0 + 1];
            d1s[r0 * 132 + c0]           = f2tf32(fmaxf(acc[mt][nt][0] + b0, 0.f));
            d1s[r0 * 132 + c0 + 1]       = f2tf32(fmaxf(acc[mt][nt][1] + b1, 0.f));
            d1s[(r0 + 8) * 132 + c0]     = f2tf32(fmaxf(acc[mt][nt][2] + b0, 0.f));
            d1s[(r0 + 8) * 132 + c0 + 1] = f2tf32(fmaxf(acc[mt][nt][3] + b1, 0.f));
        }

    // e = (e + relu(d1 @ Uo + b)) * alive
    gemm_smemA(d1s, 132, 128, uow, 128, Bs, acc, tid, wm0, wn0, g, t4);
#pragma unroll
    for (int mt = 0; mt < 4; mt++) {
        const int r0 = wm0 + mt * 16 + g;
        const float al0 = (dones[br0 + r0] == 0) ? 1.f : 0.f;
        const float al1 = (dones[br0 + r0 + 8] == 0) ? 1.f : 0.f;
#pragma unroll
        for (int nt = 0; nt < 4; nt++) {
            const int c0 = wn0 + nt * 8 + 2 * t4;
            const float b0 = uob[c0], b1 = uob[c0 + 1];
            float* p0 = e + (size_t)(br0 + r0) * 128 + c0;
            float* p1 = e + (size_t)(br0 + r0 + 8) * 128 + c0;
            const float2 e0 = *(const float2*)p0;
            const float2 e1 = *(const float2*)p1;
            float2 o0, o1;
            o0.x = (e0.x + fmaxf(acc[mt][nt][0] + b0, 0.f)) * al0;
            o0.y = (e0.y + fmaxf(acc[mt][nt][1] + b1, 0.f)) * al0;
            o1.x = (e1.x + fmaxf(acc[mt][nt][2] + b0, 0.f)) * al1;
            o1.y = (e1.y + fmaxf(acc[mt][nt][3] + b1, 0.f)) * al1;
            *(float2*)p0 = o0;
            *(float2*)p1 = o1;
        }
    }
}

// ================= kernel C: e -> v1 -> v2 -> values =================
__global__ __launch_bounds__(256) void value_fused(
    const float* __restrict__ e,
    const float* __restrict__ v1w, const float* __restrict__ v1b,
    const float* __restrict__ v2w, const float* __restrict__ v2b,
    const float* __restrict__ vow, const float* __restrict__ vob,
    float* __restrict__ values)
{
    extern __shared__ unsigned char smraw[];
    uint32_t* As  = (uint32_t*)smraw;      // 128*36
    uint32_t* Bs  = As + 128 * 36;         // 32*136
    uint32_t* v1s = Bs + 32 * 136;         // 128*260
    float* sred = (float*)(v1s + 128 * 260);  // 4*128

    const int tid = threadIdx.x;
    const int warp = tid >> 5, lane = tid & 31;
    const int g = lane >> 2, t4 = lane & 3;
    const int wm0 = (warp >> 2) * 64, wn0 = (warp & 3) * 32;
    const int br0 = blockIdx.x * 128;
    float acc[4][4][4];

    // v1 = relu(e @ W1 + b)   N=256 in 2 passes
    for (int p = 0; p < 2; p++) {
        gemm_gmemA(e + (size_t)br0 * 128, 128, 128, v1w + p * 128, 256,
                   As, Bs, acc, tid, wm0, wn0, g, t4);
#pragma unroll
        for (int mt = 0; mt < 4; mt++)
#pragma unroll
            for (int nt = 0; nt < 4; nt++) {
                const int r0 = wm0 + mt * 16 + g, c0 = wn0 + nt * 8 + 2 * t4;
                const int cg = p * 128 + c0;
                const float b0 = v1b[cg], b1 = v1b[cg + 1];
                v1s[r0 * 260 + cg]           = f2tf32(fmaxf(acc[mt][nt][0] + b0, 0.f));
                v1s[r0 * 260 + cg + 1]       = f2tf32(fmaxf(acc[mt][nt][1] + b1, 0.f));
                v1s[(r0 + 8) * 260 + cg]     = f2tf32(fmaxf(acc[mt][nt][2] + b0, 0.f));
                v1s[(r0 + 8) * 260 + cg + 1] = f2tf32(fmaxf(acc[mt][nt][3] + b1, 0.f));
            }
    }

    // v2 = relu(v1 @ W2 + b); partial = sum_n v2*vow[n]
    float part[4][2];
#pragma unroll
    for (int mt = 0; mt < 4; mt++) { part[mt][0] = 0.f; part[mt][1] = 0.f; }
    for (int p = 0; p < 2; p++) {
        gemm_smemA(v1s, 260, 256, v2w + p * 128, 256, Bs, acc, tid, wm0, wn0, g, t4);
#pragma unroll
        for (int mt = 0; mt < 4; mt++)
#pragma unroll
            for (int nt = 0; nt < 4; nt++) {
                const int c0 = wn0 + nt * 8 + 2 * t4;
                const int cg = p * 128 + c0;
                const float b0 = v2b[cg], b1 = v2b[cg + 1];
                const float w0 = vow[cg], w1 = vow[cg + 1];
                part[mt][0] = fmaf(fmaxf(acc[mt][nt][0] + b0, 0.f), w0, part[mt][0]);
                part[mt][0] = fmaf(fmaxf(acc[mt][nt][1] + b1, 0.f), w1, part[mt][0]);
                part[mt][1] = fmaf(fmaxf(acc[mt][nt][2] + b0, 0.f), w0, part[mt][1]);
                part[mt][1] = fmaf(fmaxf(acc[mt][nt][3] + b1, 0.f), w1, part[mt][1]);
            }
    }
    // reduce over t4 quad
#pragma unroll
    for (int mt = 0; mt < 4; mt++)
#pragma unroll
        for (int h = 0; h < 2; h++) {
            part[mt][h] += __shfl_xor_sync(0xffffffffu, part[mt][h], 1);
            part[mt][h] += __shfl_xor_sync(0xffffffffu, part[mt][h], 2);
        }
    __syncthreads();   // Bs no longer needed; sred region distinct anyway
    if (t4 == 0) {
        const int wn = warp & 3;
#pragma unroll
        for (int mt = 0; mt < 4; mt++)
#pragma unroll
            for (int h = 0; h < 2; h++)
                sred[wn * 128 + wm0 + mt * 16 + g + h * 8] = part[mt][h];
    }
    __syncthreads();
    if (tid < 128) {
        const float v = sred[tid] + sred[128 + tid] + sred[256 + tid] + sred[384 + tid]
                      + __ldg(vob);
        values[br0 + tid] = v;
    }
}

// ================= launch =================
extern "C" void kernel_launch(void* const* d_in, const int* in_sizes, int n_in,
                              void* d_out, int out_size)
{
    const float* hidden = (const float*)d_in[0];
    const float* obs    = (const float*)d_in[1];
    const int*   dones  = (const int*)d_in[2];
    const float* e1w = (const float*)d_in[3];
    const float* e1b = (const float*)d_in[4];
    const float* e2w = (const float*)d_in[5];
    const float* e2b = (const float*)d_in[6];
    const float* Wi  = (const float*)d_in[7];
    const float* bi  = (const float*)d_in[8];
    const float* Wh  = (const float*)d_in[9];
    const float* bhn = (const float*)d_in[10];
    const float* chw = (const float*)d_in[11];
    const float* chb = (const float*)d_in[12];
    const float* cow = (const float*)d_in[13];
    const float* cob = (const float*)d_in[14];
    const float* uhw = (const float*)d_in[15];
    const float* uhb = (const float*)d_in[16];
    const float* uow = (const float*)d_in[17];
    const float* uob = (const float*)d_in[18];
    const float* v1w = (const float*)d_in[19];
    const float* v1b = (const float*)d_in[20];
    const float* v2w = (const float*)d_in[21];
    const float* v2b = (const float*)d_in[22];
    const float* vow = (const float*)d_in[23];
    const float* vob = (const float*)d_in[24];
    float* out = (float*)d_out;

    float *gi, *e, *cat;
    cudaGetSymbolAddress((void**)&gi,  g_gi);
    cudaGetSymbolAddress((void**)&e,   g_e);
    cudaGetSymbolAddress((void**)&cat, g_cat);

    const int smD = (128 * 36 + 32 * 136 + 2 * 128 * 132) * 4;
    const int smA = (128 * 36 + 32 * 136 + 2 * 128 * 132 + 3 * 128 + 16 * 64) * 4;
    const int smB = (128 * 36 + 32 * 136 + 128 * 132) * 4;
    const int smC = (128 * 36 + 32 * 136 + 128 * 260) * 4 + 4 * 128 * 4;
    cudaFuncSetAttribute(embed_gi_fused, cudaFuncAttributeMaxDynamicSharedMemorySize, smD);
    cudaFuncSetAttribute(couple_fused,   cudaFuncAttributeMaxDynamicSharedMemorySize, smA);
    cudaFuncSetAttribute(delta_fused,    cudaFuncAttributeMaxDynamicSharedMemorySize, smB);
    cudaFuncSetAttribute(value_fused,    cudaFuncAttributeMaxDynamicSharedMemorySize, smC);

    embed_gi_fused<<<512, 256, smD>>>(obs, e1w, e1b, e2w, e2b, Wi, bi, gi);
    gru_kernel<<<128, 384>>>(gi, dones, Wh, bhn, hidden, e, out);

    for (int it = 0; it < 2; it++) {
        couple_fused<<<512, 256, smA>>>(e, chw, chb, cow, cob, dones, cat);
        delta_fused<<<512, 256, smB>>>(cat, uhw, uhb, uow, uob, dones, e);
    }

    value_fused<<<512, 256, smC>>>(e, v1w, v1b, v2w, v2b, vow, vob, out + 65536);
}